// round 2
// baseline (speedup 1.0000x reference)
#include <cuda_runtime.h>
#include <math.h>

// Problem dims (fixed by reference)
#define BB 256      // batch
#define TT 500      // time steps
#define II 256      // input dim
#define HH 512      // hidden dim
#define GG 2048     // 4*H
#define OO 100      // output dim
#define NBLK 128    // persistent blocks (<= 148 SMs -> all resident)

// Scratch (allocation-free: __device__ globals)
__device__ float g_xg[(size_t)TT * BB * GG];   // [T][B][4H] input projections (+bx+bh)
__device__ float g_hbuf[2][BB * HH];           // double-buffered hidden state
__device__ unsigned g_bar_count;
__device__ volatile unsigned g_epoch;

// ---------------- Tiled GEMM config ----------------
#define Bb 64
#define Bn 64
#define Bk 16

// ---------------------------------------------------------------------------
// Kernel 1: xg[t][b][g] = sum_i x[b][t][i] * Wx[g][i] + bx[g] + bh[g]
// M = T*B rows (row m -> t = m/256, b = m%256). Grid (2000, 32), 256 thr.
// ---------------------------------------------------------------------------
__global__ __launch_bounds__(256) void xg_gemm(const float* __restrict__ x,
                                               const float* __restrict__ Wx,
                                               const float* __restrict__ bx,
                                               const float* __restrict__ bh) {
    __shared__ __align__(16) float As[Bk][Bb];
    __shared__ __align__(16) float Bs[Bk][Bn];

    const int mBase = blockIdx.x * Bb;
    const int nBase = blockIdx.y * Bn;
    const int t  = mBase >> 8;
    const int b0 = mBase & 255;

    const int tid = threadIdx.x;
    const int tx = tid & 15;
    const int ty = tid >> 4;
    const int lr  = tid >> 2;
    const int lk4 = (tid & 3) << 2;

    const float* Abase = x + (size_t)b0 * TT * II + (size_t)t * II;
    const size_t aRowStride = (size_t)TT * II;

    float acc[4][4] = {};

    for (int k0 = 0; k0 < II; k0 += Bk) {
        float4 av = *reinterpret_cast<const float4*>(Abase + (size_t)lr * aRowStride + k0 + lk4);
        float4 bv = *reinterpret_cast<const float4*>(Wx + (size_t)(nBase + lr) * II + k0 + lk4);
        As[lk4 + 0][lr] = av.x; As[lk4 + 1][lr] = av.y;
        As[lk4 + 2][lr] = av.z; As[lk4 + 3][lr] = av.w;
        Bs[lk4 + 0][lr] = bv.x; Bs[lk4 + 1][lr] = bv.y;
        Bs[lk4 + 2][lr] = bv.z; Bs[lk4 + 3][lr] = bv.w;
        __syncthreads();
#pragma unroll
        for (int kk = 0; kk < Bk; kk++) {
            float4 a  = *reinterpret_cast<const float4*>(&As[kk][ty << 2]);
            float4 bb = *reinterpret_cast<const float4*>(&Bs[kk][tx << 2]);
            float ar[4] = {a.x, a.y, a.z, a.w};
            float br[4] = {bb.x, bb.y, bb.z, bb.w};
#pragma unroll
            for (int i = 0; i < 4; i++)
#pragma unroll
                for (int j = 0; j < 4; j++)
                    acc[i][j] = fmaf(ar[i], br[j], acc[i][j]);
        }
        __syncthreads();
    }

#pragma unroll
    for (int j = 0; j < 4; j++) {
        int n = nBase + (tx << 2) + j;
        float bias = bx[n] + bh[n];
#pragma unroll
        for (int i = 0; i < 4; i++) {
            int m = mBase + (ty << 2) + i;
            g_xg[(size_t)m * GG + n] = acc[i][j] + bias;
        }
    }
}

// ---------------------------------------------------------------------------
// Grid-wide software barrier (all threads must have issued __threadfence()
// for their global stores before calling).
// ---------------------------------------------------------------------------
__device__ __forceinline__ void grid_bar(unsigned step) {
    __syncthreads();
    if (threadIdx.x == 0) {
        unsigned arrived = atomicAdd(&g_bar_count, 1);
        if (arrived == NBLK - 1) {
            g_bar_count = 0;
            __threadfence();
            g_epoch = step + 1;
        } else {
            while (g_epoch <= step) __nanosleep(64);
            __threadfence();
        }
    }
    __syncthreads();
}

// ---------------------------------------------------------------------------
// Kernel 2: persistent LSTM recurrence. 128 blocks x 256 threads.
// Block (bm, bn): bm in [0,4) -> 64 batch rows; bn in [0,32) -> 16 hidden
// cols, but across ALL FOUR gates (strided column mapping). So each block
// can do the full cell update for its (64 x 16) slice with gates in smem
// and c in registers. h is double-buffered in global -> 1 barrier/step.
// ---------------------------------------------------------------------------
__global__ __launch_bounds__(256) void lstm_persistent(const float* __restrict__ Wh) {
    __shared__ __align__(16) float As[Bk][Bb];
    __shared__ __align__(16) float Bs[Bk][Bn];
    __shared__ __align__(16) float sg[64][68];   // gates tile (padded)

    const int tid = threadIdx.x;
    const int bm = blockIdx.x >> 5;       // 0..3
    const int bn = blockIdx.x & 31;       // 0..31
    const int m0 = bm << 6;               // batch row base
    const int j0 = bn << 4;               // hidden col base (16 wide)

    const int tx = tid & 15;
    const int ty = tid >> 4;
    const int lm  = tid >> 2;             // 0..63: A-row / B-col index
    const int lk4 = (tid & 3) << 2;       // 0,4,8,12

    // B column mapping: c in [0,64) -> gate = c/16, col = j0 + c%16
    const int ncol = ((lm >> 4) << 9) + j0 + (lm & 15);
    const float* WhRow = Wh + (size_t)ncol * HH;   // L1-resident across steps

    // epilogue column base for this thread (4 consecutive cols, one gate)
    const int cb = tx << 2;
    const int ncolE = ((cb >> 4) << 9) + j0 + (cb & 15);

    // pointwise mapping: element el = tid*4+e -> row pm, col pj+e
    const int pm = tid >> 2;
    const int pj = (tid << 2) & 15;

    float c_reg[4] = {0.f, 0.f, 0.f, 0.f};

    for (int t = 0; t < TT; ++t) {
        const int p = t & 1;
        const float* hRead = g_hbuf[p];
        float acc[4][4] = {};

        const float* aPtr = hRead + (size_t)(m0 + lm) * HH + lk4;

        // software-pipelined GEMM over K = 512
        float4 aN = __ldcg(reinterpret_cast<const float4*>(aPtr));
        float4 bN = *reinterpret_cast<const float4*>(WhRow + lk4);
#pragma unroll 1
        for (int k0 = 0; k0 < HH; k0 += Bk) {
            As[lk4 + 0][lm] = aN.x; As[lk4 + 1][lm] = aN.y;
            As[lk4 + 2][lm] = aN.z; As[lk4 + 3][lm] = aN.w;
            Bs[lk4 + 0][lm] = bN.x; Bs[lk4 + 1][lm] = bN.y;
            Bs[lk4 + 2][lm] = bN.z; Bs[lk4 + 3][lm] = bN.w;
            __syncthreads();
            if (k0 + Bk < HH) {
                aN = __ldcg(reinterpret_cast<const float4*>(aPtr + k0 + Bk));
                bN = *reinterpret_cast<const float4*>(WhRow + k0 + Bk + lk4);
            }
#pragma unroll
            for (int kk = 0; kk < Bk; kk++) {
                float4 a  = *reinterpret_cast<const float4*>(&As[kk][ty << 2]);
                float4 bb = *reinterpret_cast<const float4*>(&Bs[kk][tx << 2]);
                float ar[4] = {a.x, a.y, a.z, a.w};
                float br[4] = {bb.x, bb.y, bb.z, bb.w};
#pragma unroll
                for (int i = 0; i < 4; i++)
#pragma unroll
                    for (int j = 0; j < 4; j++)
                        acc[i][j] = fmaf(ar[i], br[j], acc[i][j]);
            }
            __syncthreads();
        }

        // add xg[t] and stage gates tile to smem
        const float* xg_t = g_xg + ((size_t)t * BB + m0) * GG;
#pragma unroll
        for (int i = 0; i < 4; i++) {
            int m = (ty << 2) + i;
            float4 xv = __ldcg(reinterpret_cast<const float4*>(xg_t + (size_t)m * GG + ncolE));
            acc[i][0] += xv.x; acc[i][1] += xv.y;
            acc[i][2] += xv.z; acc[i][3] += xv.w;
            *reinterpret_cast<float4*>(&sg[m][cb]) =
                make_float4(acc[i][0], acc[i][1], acc[i][2], acc[i][3]);
        }
        __syncthreads();

        // pointwise cell update: 4 elements per thread, c in registers
        float* hw = g_hbuf[p ^ 1] + (size_t)(m0 + pm) * HH + j0 + pj;
        float hv[4];
#pragma unroll
        for (int e = 0; e < 4; e++) {
            float iv = sg[pm][ 0 + pj + e];
            float fv = sg[pm][16 + pj + e];
            float gv = sg[pm][32 + pj + e];
            float ov = sg[pm][48 + pj + e];
            iv = 1.0f / (1.0f + __expf(-iv));
            fv = 1.0f / (1.0f + __expf(-fv));
            gv = tanhf(gv);
            ov = 1.0f / (1.0f + __expf(-ov));
            float cc = c_reg[e] * fv + iv * gv;
            c_reg[e] = cc;
            hv[e] = ov * tanhf(cc);
        }
        *reinterpret_cast<float4*>(hw) = make_float4(hv[0], hv[1], hv[2], hv[3]);

        __threadfence();   // make h stores visible before barrier publish
        grid_bar(t);
    }
}

// ---------------------------------------------------------------------------
// Kernel 3: init h buffers + barrier state
// ---------------------------------------------------------------------------
__global__ __launch_bounds__(256) void init_kernel() {
    int i = blockIdx.x * blockDim.x + threadIdx.x;
    if (i < BB * HH) { g_hbuf[0][i] = 0.0f; g_hbuf[1][i] = 0.0f; }
    if (i == 0) { g_bar_count = 0; g_epoch = 0; }
}

// ---------------------------------------------------------------------------
// Kernel 4: final FC: out[b][o] = h[b] . Wfc[o] + bfc[o]
// Final h lives in buffer written at t=TT-1: index ((TT-1)&1)^1 == TT&1.
// ---------------------------------------------------------------------------
__global__ __launch_bounds__(256) void fc_kernel(const float* __restrict__ Wfc,
                                                 const float* __restrict__ bfc,
                                                 float* __restrict__ out) {
    int idx = blockIdx.x * blockDim.x + threadIdx.x;
    if (idx >= BB * OO) return;
    int b = idx / OO;
    int o = idx - b * OO;
    const float* hr = g_hbuf[TT & 1] + (size_t)b * HH;
    const float* wr = Wfc + (size_t)o * HH;
    float s = bfc[o];
#pragma unroll 8
    for (int k = 0; k < HH; k++) s = fmaf(hr[k], wr[k], s);
    out[idx] = s;
}

// ---------------------------------------------------------------------------
extern "C" void kernel_launch(void* const* d_in, const int* in_sizes, int n_in,
                              void* d_out, int out_size) {
    const float* x   = (const float*)d_in[0];  // [B,T,I]
    const float* Wx  = (const float*)d_in[1];  // [4H,I]
    const float* bx  = (const float*)d_in[2];  // [4H]
    const float* Wh  = (const float*)d_in[3];  // [4H,H]
    const float* bh  = (const float*)d_in[4];  // [4H]
    const float* Wfc = (const float*)d_in[5];  // [O,H]
    const float* bfc = (const float*)d_in[6];  // [O]
    float* out = (float*)d_out;                // [B,O]

    init_kernel<<<(BB * HH + 255) / 256, 256>>>();

    {
        dim3 grid((TT * BB) / Bb, GG / Bn);
        xg_gemm<<<grid, 256>>>(x, Wx, bx, bh);
    }

    lstm_persistent<<<NBLK, 256>>>(Wh);

    fc_kernel<<<(BB * OO + 255) / 256, 256>>>(Wfc, bfc, out);
}